// round 3
// baseline (speedup 1.0000x reference)
#include <cuda_runtime.h>
#include <cstdint>

// Problem constants
#define N_ROWS   16384      // 16*32*32 vectors
#define DIMS     256
#define K_CODES  8192
#define OUT_ELEMS 4194304   // 16*256*32*32
#define LOSS_OFF  4194304
#define IDX_OFF   4194305

// Scratch (device globals: allocation-free rule)
__device__ float g_xr[N_ROWS * DIMS];   // transposed x, [n][c]
__device__ float g_xx[N_ROWS];          // ||x_n||^2
__device__ float g_ce[K_CODES];         // ||e_k||^2
__device__ int   g_idx[N_ROWS];
__device__ float g_part[4096];

static __device__ __forceinline__ void ffma2(unsigned long long& d,
                                             unsigned long long a,
                                             unsigned long long b) {
    asm("fma.rn.f32x2 %0, %1, %2, %0;" : "+l"(d) : "l"(a), "l"(b));
}
static __device__ __forceinline__ float2 u2f2(unsigned long long u) {
    float2 f;
    asm("mov.b64 {%0, %1}, %2;" : "=f"(f.x), "=f"(f.y) : "l"(u));
    return f;
}

// ---------------------------------------------------------------------------
// 1) Transpose x [b,c,h,w] -> g_xr [n= b*1024+hw][c]  (exact copy)
// ---------------------------------------------------------------------------
__global__ void k_trx(const float* __restrict__ x) {
    __shared__ float t[32][33];
    const int b = blockIdx.z, c0 = blockIdx.y * 32, hw0 = blockIdx.x * 32;
    const int tx = threadIdx.x, ty = threadIdx.y;
#pragma unroll
    for (int j = 0; j < 4; j++) {
        int c = c0 + ty + j * 8;
        t[ty + j * 8][tx] = x[(size_t)b * 262144 + (size_t)c * 1024 + hw0 + tx];
    }
    __syncthreads();
#pragma unroll
    for (int j = 0; j < 4; j++) {
        int hw = hw0 + ty + j * 8;
        g_xr[(size_t)(b * 1024 + hw) * DIMS + c0 + tx] = t[tx][ty + j * 8];
    }
}

// ---------------------------------------------------------------------------
// 2) Row norms ||x_n||^2 (fp32, tree-ish partial sums), coalesced over hw
// ---------------------------------------------------------------------------
__global__ void k_xx(const float* __restrict__ x) {
    int n = blockIdx.x * 256 + threadIdx.x;
    int b = n >> 10, hw = n & 1023;
    const float* p = x + (size_t)b * 262144 + hw;
    float s0 = 0.f, s1 = 0.f, s2 = 0.f, s3 = 0.f;
#pragma unroll 8
    for (int c = 0; c < 256; c += 4) {
        float v0 = p[(size_t)(c + 0) * 1024];
        float v1 = p[(size_t)(c + 1) * 1024];
        float v2 = p[(size_t)(c + 2) * 1024];
        float v3 = p[(size_t)(c + 3) * 1024];
        s0 = fmaf(v0, v0, s0); s1 = fmaf(v1, v1, s1);
        s2 = fmaf(v2, v2, s2); s3 = fmaf(v3, v3, s3);
    }
    g_xx[n] = (s0 + s1) + (s2 + s3);
}

// ---------------------------------------------------------------------------
// 3) Codebook norms ||e_k||^2 (one warp per code row, fp32)
// ---------------------------------------------------------------------------
__global__ void k_pe(const float* __restrict__ e) {
    int w = threadIdx.x >> 5, lane = threadIdx.x & 31;
    int row = blockIdx.x * 8 + w;
    const float4* p = (const float4*)(e + (size_t)row * DIMS);
    float4 v0 = p[lane], v1 = p[lane + 32];
    float s = v0.x * v0.x + v0.y * v0.y + v0.z * v0.z + v0.w * v0.w +
              v1.x * v1.x + v1.y * v1.y + v1.z * v1.z + v1.w * v1.w;
#pragma unroll
    for (int off = 16; off; off >>= 1) s += __shfl_xor_sync(0xffffffffu, s, off);
    if (lane == 0) g_ce[row] = s;
}

// ---------------------------------------------------------------------------
// 4) Main: fused exact-fp32 GEMM + running argmin.
//    Block: 128 rows x all 8192 codes. X tile resident in SMEM (128 KB),
//    E streamed from input (double-buffered 16 KB). Packed f32x2 FMA.
// ---------------------------------------------------------------------------
__global__ void __launch_bounds__(512, 1) k_main(const float* __restrict__ E) {
    extern __shared__ float2 sm[];
    float2* Xf = sm;               // [128 k-pairs][128 rows]
    float2* Es = sm + 128 * 128;   // [2][16 k-pairs][128 codes]

    const int tid = threadIdx.x;
    const int lane = tid & 31;
    const int wy = tid >> 5;           // warp id 0..15 -> 8 rows each
    const int row0 = blockIdx.x * 128;
    const int m0 = wy * 8;

    // --- load full X block into SMEM (pair layout) ---
#pragma unroll
    for (int j = 0; j < 16; j++) {
        int fid = j * 512 + tid;       // 8192 float4 total
        int m = fid >> 6;              // row within tile
        int kc = fid & 63;             // float4 index along k
        float4 v = *(const float4*)(g_xr + (size_t)(row0 + m) * DIMS + kc * 4);
        Xf[(kc * 2 + 0) * 128 + m] = make_float2(v.x, v.y);
        Xf[(kc * 2 + 1) * 128 + m] = make_float2(v.z, v.w);
    }

    float xxv[8];
#pragma unroll
    for (int r = 0; r < 8; r++) xxv[r] = g_xx[row0 + m0 + r];

    float minv[8];
    int mini[8];
#pragma unroll
    for (int r = 0; r < 8; r++) { minv[r] = 3.402823466e38f; mini[r] = 0x7fffffff; }

    unsigned long long acc[8][4];
#pragma unroll
    for (int r = 0; r < 8; r++)
#pragma unroll
        for (int c = 0; c < 4; c++) acc[r][c] = 0ull;

    // --- prefetch E tile for it=0 (chunk 0, ktile 0) ---
    float4 na, nb;
    {
        const float* gb = E;  // chunk 0, ktile 0
        na = *(const float4*)(gb + (size_t)(tid >> 3) * DIMS + (tid & 7) * 4);
        nb = *(const float4*)(gb + (size_t)((tid + 512) >> 3) * DIMS + ((tid + 512) & 7) * 4);
    }
    {
        int id = tid, code = id >> 3, kc = id & 7;
        Es[(0 * 16 + kc * 2 + 0) * 128 + code] = make_float2(na.x, na.y);
        Es[(0 * 16 + kc * 2 + 1) * 128 + code] = make_float2(na.z, na.w);
        id = tid + 512; code = id >> 3; kc = id & 7;
        Es[(0 * 16 + kc * 2 + 0) * 128 + code] = make_float2(nb.x, nb.y);
        Es[(0 * 16 + kc * 2 + 1) * 128 + code] = make_float2(nb.z, nb.w);
    }
    __syncthreads();

    int buf = 0;
    for (int it = 0; it < 512; ++it) {
        const int chunk = it >> 3;
        const int ktile = it & 7;

        // prefetch next E tile to registers
        if (it < 511) {
            int it2 = it + 1;
            const float* gb = E + (size_t)(it2 >> 3) * 128 * DIMS + (it2 & 7) * 32;
            na = *(const float4*)(gb + (size_t)(tid >> 3) * DIMS + (tid & 7) * 4);
            nb = *(const float4*)(gb + (size_t)((tid + 512) >> 3) * DIMS + ((tid + 512) & 7) * 4);
        }

        const float2* ebase = Es + buf * 16 * 128;
#pragma unroll
        for (int k2 = 0; k2 < 16; k2++) {
            const float2* xr = Xf + (ktile * 16 + k2) * 128 + m0;
            ulonglong2 A01 = *(const ulonglong2*)(xr + 0);
            ulonglong2 A23 = *(const ulonglong2*)(xr + 2);
            ulonglong2 A45 = *(const ulonglong2*)(xr + 4);
            ulonglong2 A67 = *(const ulonglong2*)(xr + 6);
            const float2* er = ebase + k2 * 128;
            ulonglong2 B01 = *(const ulonglong2*)(er + lane * 2);
            ulonglong2 B23 = *(const ulonglong2*)(er + 64 + lane * 2);
            unsigned long long a[8] = {A01.x, A01.y, A23.x, A23.y,
                                       A45.x, A45.y, A67.x, A67.y};
            unsigned long long b[4] = {B01.x, B01.y, B23.x, B23.y};
#pragma unroll
            for (int r = 0; r < 8; r++)
#pragma unroll
                for (int c = 0; c < 4; c++) ffma2(acc[r][c], a[r], b[c]);
        }

        // chunk epilogue: fold accumulators into running argmin, reset
        if (ktile == 7) {
            const int cb = chunk * 128;
#pragma unroll
            for (int c = 0; c < 4; c++) {
                int code = cb + lane * 2 + (c & 1) + (c >> 1) * 64;
                float cev = g_ce[code];
#pragma unroll
                for (int r = 0; r < 8; r++) {
                    float2 p = u2f2(acc[r][c]);
                    float t = p.x + p.y;
                    float s = (xxv[r] + cev) - 2.0f * t;
                    if (s < minv[r] || (s == minv[r] && code < mini[r])) {
                        minv[r] = s; mini[r] = code;
                    }
                    acc[r][c] = 0ull;
                }
            }
        }

        // fill the other buffer, single barrier per tile
        if (it < 511) {
            int nbuf = buf ^ 1;
            int id = tid, code = id >> 3, kc = id & 7;
            Es[(nbuf * 16 + kc * 2 + 0) * 128 + code] = make_float2(na.x, na.y);
            Es[(nbuf * 16 + kc * 2 + 1) * 128 + code] = make_float2(na.z, na.w);
            id = tid + 512; code = id >> 3; kc = id & 7;
            Es[(nbuf * 16 + kc * 2 + 0) * 128 + code] = make_float2(nb.x, nb.y);
            Es[(nbuf * 16 + kc * 2 + 1) * 128 + code] = make_float2(nb.z, nb.w);
            __syncthreads();
            buf = nbuf;
        }
    }

    // lane reduction: each warp owns 8 rows, lanes hold disjoint code sets
#pragma unroll
    for (int r = 0; r < 8; r++) {
        float v = minv[r];
        int i = mini[r];
#pragma unroll
        for (int off = 16; off; off >>= 1) {
            float ov = __shfl_down_sync(0xffffffffu, v, off);
            int   oi = __shfl_down_sync(0xffffffffu, i, off);
            if (ov < v || (ov == v && oi < i)) { v = ov; i = oi; }
        }
        if (lane == 0) g_idx[row0 + m0 + r] = i;
    }
}

// ---------------------------------------------------------------------------
// 5) Gather codebook rows -> out (b,c,h,w), write indices, loss partials
// ---------------------------------------------------------------------------
__global__ void k_out(const float* __restrict__ x, const float* __restrict__ e,
                      float* __restrict__ dout) {
    __shared__ float t[32][33];
    __shared__ int sidx[32];
    __shared__ float red[256];
    const int b = blockIdx.z, c0 = blockIdx.y * 32, hw0 = blockIdx.x * 32;
    const int tx = threadIdx.x, ty = threadIdx.y;

    if (ty == 0) {
        int n = b * 1024 + hw0 + tx;
        int i = g_idx[n];
        sidx[tx] = i;
        if (blockIdx.y == 0) dout[IDX_OFF + n] = (float)i;
    }
    __syncthreads();
#pragma unroll
    for (int j = 0; j < 4; j++) {
        int hwl = ty + j * 8;
        t[hwl][tx] = e[(size_t)sidx[hwl] * DIMS + c0 + tx];
    }
    __syncthreads();
    float lacc = 0.f;
#pragma unroll
    for (int j = 0; j < 4; j++) {
        int cl = ty + j * 8;
        size_t o = (size_t)b * 262144 + (size_t)(c0 + cl) * 1024 + hw0 + tx;
        float q = t[tx][cl];
        dout[o] = q;
        float d = q - x[o];
        lacc = fmaf(d, d, lacc);
    }
    int tid = ty * 32 + tx;
    red[tid] = lacc;
    __syncthreads();
    for (int s = 128; s; s >>= 1) {
        if (tid < s) red[tid] += red[tid + s];
        __syncthreads();
    }
    if (tid == 0) g_part[(blockIdx.z * 8 + blockIdx.y) * 32 + blockIdx.x] = red[0];
}

// ---------------------------------------------------------------------------
// 6) Final loss reduction (double accumulation, deterministic)
// ---------------------------------------------------------------------------
__global__ void k_loss(float* __restrict__ dout) {
    __shared__ double rd[256];
    double s = 0.0;
    for (int i = threadIdx.x; i < 4096; i += 256) s += (double)g_part[i];
    rd[threadIdx.x] = s;
    __syncthreads();
    for (int st = 128; st; st >>= 1) {
        if (threadIdx.x < st) rd[threadIdx.x] += rd[threadIdx.x + st];
        __syncthreads();
    }
    if (threadIdx.x == 0)
        dout[LOSS_OFF] = (float)(rd[0] * (1.25 / (double)OUT_ELEMS));
}

// ---------------------------------------------------------------------------
extern "C" void kernel_launch(void* const* d_in, const int* in_sizes, int n_in,
                              void* d_out, int out_size) {
    const float* x = (const float*)d_in[0];   // [16,256,32,32]
    const float* e = (const float*)d_in[1];   // [8192,256]
    float* out = (float*)d_out;

    cudaFuncSetAttribute(k_main, cudaFuncAttributeMaxDynamicSharedMemorySize,
                         163840);

    k_trx<<<dim3(32, 8, 16), dim3(32, 8)>>>(x);
    k_xx<<<64, 256>>>(x);
    k_pe<<<1024, 256>>>(e);
    k_main<<<128, 512, 163840>>>(e);
    k_out<<<dim3(32, 8, 16), dim3(32, 8)>>>(x, e, out);
    k_loss<<<1, 256>>>(out);
}

// round 7
// speedup vs baseline: 3.0898x; 3.0898x over previous
#include <cuda_runtime.h>
#include <cuda_bf16.h>
#include <cstdint>

#define N_ROWS   16384
#define DIMS     256
#define K_CODES  8192
#define OUT_ELEMS 4194304
#define LOSS_OFF  4194304
#define IDX_OFF   4194305
#define NGROUP   1024          // 8192 codes / 8 per group
#define MARGIN   0.125f

// device scratch (allocation-free rule)
__device__ float g_xr[N_ROWS * DIMS];            // transposed x fp32
__device__ __nv_bfloat16 g_xb[N_ROWS * DIMS];    // transposed x bf16
__device__ __nv_bfloat16 g_ebh[K_CODES * DIMS];  // E bf16
__device__ float g_xx[N_ROWS];
__device__ float g_ce[K_CODES];
__device__ __nv_bfloat16 g_cmin[N_ROWS * NGROUP]; // approx 8-code group mins
__device__ int   g_idx[N_ROWS];
__device__ float g_part[4096];

// ---------------- PTX helpers ----------------
static __device__ __forceinline__ uint32_t smem_u32(const void* p) {
    uint32_t a;
    asm("{ .reg .u64 t; cvta.to.shared.u64 t, %1; cvt.u32.u64 %0, t; }"
        : "=r"(a) : "l"(p));
    return a;
}
#define CP16(dst, src) asm volatile("cp.async.cg.shared.global [%0], [%1], 16;" :: "r"(dst), "l"(src))
#define CP_COMMIT()    asm volatile("cp.async.commit_group;" ::: "memory")
#define CP_WAIT0()     asm volatile("cp.async.wait_group 0;" ::: "memory")

#define LDSM_X4(r0, r1, r2, r3, a) \
    asm volatile("ldmatrix.sync.aligned.m8n8.x4.shared.b16 {%0,%1,%2,%3}, [%4];" \
        : "=r"(r0), "=r"(r1), "=r"(r2), "=r"(r3) : "r"(a))
#define LDSM_X2(r0, r1, a) \
    asm volatile("ldmatrix.sync.aligned.m8n8.x2.shared.b16 {%0,%1}, [%2];" \
        : "=r"(r0), "=r"(r1) : "r"(a))
#define MMA16816(d, a, b) \
    asm volatile("mma.sync.aligned.m16n8k16.row.col.f32.bf16.bf16.f32 " \
        "{%0,%1,%2,%3}, {%4,%5,%6,%7}, {%8,%9}, {%0,%1,%2,%3};" \
        : "+f"((d)[0]), "+f"((d)[1]), "+f"((d)[2]), "+f"((d)[3]) \
        : "r"((a)[0]), "r"((a)[1]), "r"((a)[2]), "r"((a)[3]), "r"((b)[0]), "r"((b)[1]))

// swizzled 16B-unit offset within a [128 rows x 512B] tile
static __device__ __forceinline__ uint32_t sw_off(int r, int u) {
    return ((uint32_t)r << 9) + (uint32_t)(((u ^ (r & 7)) & 31) << 4);
}

// SMEM map for k_gemm (bytes)
#define SM_X   0
#define SM_E0  65536
#define SM_E1  131072
#define SM_CE  196608
#define SMEM_SZ 229376

// ---------------------------------------------------------------------------
// 1) transpose: x [b,c,h,w] -> g_xr fp32 and g_xb bf16, [n][c]
__global__ void k_trx(const float* __restrict__ x) {
    __shared__ float t[32][33];
    const int b = blockIdx.z, c0 = blockIdx.y * 32, hw0 = blockIdx.x * 32;
    const int tx = threadIdx.x, ty = threadIdx.y;
#pragma unroll
    for (int j = 0; j < 4; j++)
        t[ty + j * 8][tx] = x[(size_t)b * 262144 + (size_t)(c0 + ty + j * 8) * 1024 + hw0 + tx];
    __syncthreads();
#pragma unroll
    for (int j = 0; j < 4; j++) {
        int n = b * 1024 + hw0 + ty + j * 8;
        float v = t[tx][ty + j * 8];
        g_xr[(size_t)n * DIMS + c0 + tx] = v;
        g_xb[(size_t)n * DIMS + c0 + tx] = __float2bfloat16_rn(v);
    }
}

// 2) ||x||^2
__global__ void k_xx(const float* __restrict__ x) {
    int n = blockIdx.x * 256 + threadIdx.x;
    int b = n >> 10, hw = n & 1023;
    const float* p = x + (size_t)b * 262144 + hw;
    float s0 = 0.f, s1 = 0.f, s2 = 0.f, s3 = 0.f;
#pragma unroll 8
    for (int c = 0; c < 256; c += 4) {
        float v0 = p[(size_t)(c + 0) * 1024], v1 = p[(size_t)(c + 1) * 1024];
        float v2 = p[(size_t)(c + 2) * 1024], v3 = p[(size_t)(c + 3) * 1024];
        s0 = fmaf(v0, v0, s0); s1 = fmaf(v1, v1, s1);
        s2 = fmaf(v2, v2, s2); s3 = fmaf(v3, v3, s3);
    }
    g_xx[n] = (s0 + s1) + (s2 + s3);
}

// 3) ||e||^2
__global__ void k_pe(const float* __restrict__ e) {
    int w = threadIdx.x >> 5, lane = threadIdx.x & 31;
    int row = blockIdx.x * 8 + w;
    const float4* p = (const float4*)(e + (size_t)row * DIMS);
    float4 v0 = p[lane], v1 = p[lane + 32];
    float s = v0.x * v0.x + v0.y * v0.y + v0.z * v0.z + v0.w * v0.w +
              v1.x * v1.x + v1.y * v1.y + v1.z * v1.z + v1.w * v1.w;
#pragma unroll
    for (int off = 16; off; off >>= 1) s += __shfl_xor_sync(0xffffffffu, s, off);
    if (lane == 0) g_ce[row] = s;
}

// 4) E -> bf16
__global__ void k_eb(const float* __restrict__ e) {
    int i4 = blockIdx.x * 256 + threadIdx.x;  // over 524288 float4
    float4 v = ((const float4*)e)[i4];
    uint32_t lo = ((uint32_t)__bfloat16_as_ushort(__float2bfloat16_rn(v.y)) << 16) |
                  (uint32_t)__bfloat16_as_ushort(__float2bfloat16_rn(v.x));
    uint32_t hi = ((uint32_t)__bfloat16_as_ushort(__float2bfloat16_rn(v.w)) << 16) |
                  (uint32_t)__bfloat16_as_ushort(__float2bfloat16_rn(v.z));
    ((uint2*)g_ebh)[i4] = make_uint2(lo, hi);
}

// ---------------------------------------------------------------------------
// 5) Sweep 1: bf16 mma.sync GEMM, approx s = ce - 2*dot, per-8-code group mins.
//    grid 128 (row blocks of 128), block 256 = 8 warps (4 m-groups x 2 n-groups).
//    Warp tile 32 rows x 64 codes; chunk = 128 codes; 64 chunks.
// ---------------------------------------------------------------------------
__global__ void __launch_bounds__(256, 1) k_gemm() {
    extern __shared__ char smem[];
    const uint32_t sb = smem_u32(smem);
    const int tid = threadIdx.x, lane = tid & 31, wid = tid >> 5;
    const int warp_m = wid & 3, warp_n = wid >> 2;
    const int m_base = warp_m * 32, n_base = warp_n * 64;
    const int row0 = blockIdx.x * 128;

    // prologue: X tile (swizzled), ce table, E chunk0 via cp.async
#pragma unroll
    for (int j = 0; j < 16; j++) {
        int idx = tid + j * 256;           // 4096 16B units
        int r = idx >> 5, u = idx & 31;
        CP16(sb + SM_X + sw_off(r, u), g_xb + (size_t)(row0 + r) * DIMS + u * 8);
    }
#pragma unroll
    for (int j = 0; j < 8; j++) {
        int idx = tid + j * 256;           // 2048 units of ce
        CP16(sb + SM_CE + idx * 16, g_ce + idx * 4);
    }
#pragma unroll
    for (int j = 0; j < 16; j++) {
        int idx = tid + j * 256;
        int r = idx >> 5, u = idx & 31;
        CP16(sb + SM_E0 + sw_off(r, u), g_ebh + (size_t)r * DIMS + u * 8);
    }
    CP_COMMIT();

    // per-lane ldmatrix address components
    const int a_r = (lane & 15);           // row within 16-row tile
    const int a_u = (lane >> 4);           // 0/1 -> klo/khi unit
    const int b_r = (lane & 7);
    const int b_u = ((lane >> 3) & 1);

    for (int c = 0; c < 64; c++) {
        CP_WAIT0();
        __syncthreads();                   // chunk c resident; prev buf free
        const uint32_t eb = sb + ((c & 1) ? SM_E1 : SM_E0);
        if (c < 63) {                      // prefetch chunk c+1 into other buf
            const uint32_t nb = sb + ((c & 1) ? SM_E0 : SM_E1);
            const __nv_bfloat16* src = g_ebh + (size_t)(c + 1) * 128 * DIMS;
#pragma unroll
            for (int j = 0; j < 16; j++) {
                int idx = tid + j * 256;
                int r = idx >> 5, u = idx & 31;
                CP16(nb + sw_off(r, u), src + (size_t)r * DIMS + u * 8);
            }
            CP_COMMIT();
        }

        float acc[2][8][4];
#pragma unroll
        for (int mt = 0; mt < 2; mt++)
#pragma unroll
            for (int nt = 0; nt < 8; nt++)
#pragma unroll
                for (int q = 0; q < 4; q++) acc[mt][nt][q] = 0.f;

#pragma unroll
        for (int kt = 0; kt < 16; kt++) {
            uint32_t a[2][4], b[8][2];
#pragma unroll
            for (int mt = 0; mt < 2; mt++) {
                uint32_t addr = sb + SM_X +
                    sw_off(m_base + mt * 16 + a_r, kt * 2 + a_u);
                LDSM_X4(a[mt][0], a[mt][1], a[mt][2], a[mt][3], addr);
            }
#pragma unroll
            for (int nt = 0; nt < 8; nt++) {
                uint32_t addr = eb + sw_off(n_base + nt * 8 + b_r, kt * 2 + b_u);
                LDSM_X2(b[nt][0], b[nt][1], addr);
            }
#pragma unroll
            for (int mt = 0; mt < 2; mt++)
#pragma unroll
                for (int nt = 0; nt < 8; nt++)
                    MMA16816(acc[mt][nt], a[mt], b[nt]);
        }

        // epilogue: s = ce - 2*t; min over each 8-code group; write g_cmin
#pragma unroll
        for (int nt = 0; nt < 8; nt++) {
            int col = c * 128 + n_base + nt * 8 + (lane & 3) * 2;
            float2 ce2;
            asm volatile("ld.shared.v2.f32 {%0,%1}, [%2];"
                         : "=f"(ce2.x), "=f"(ce2.y)
                         : "r"(sb + SM_CE + (uint32_t)col * 4));
#pragma unroll
            for (int mt = 0; mt < 2; mt++) {
                float vlo = fminf(fmaf(-2.f, acc[mt][nt][0], ce2.x),
                                  fmaf(-2.f, acc[mt][nt][1], ce2.y));
                float vhi = fminf(fmaf(-2.f, acc[mt][nt][2], ce2.x),
                                  fmaf(-2.f, acc[mt][nt][3], ce2.y));
                vlo = fminf(vlo, __shfl_xor_sync(0xffffffffu, vlo, 1));
                vlo = fminf(vlo, __shfl_xor_sync(0xffffffffu, vlo, 2));
                vhi = fminf(vhi, __shfl_xor_sync(0xffffffffu, vhi, 1));
                vhi = fminf(vhi, __shfl_xor_sync(0xffffffffu, vhi, 2));
                if ((lane & 3) == 0) {
                    int grp = c * 16 + warp_n * 8 + nt;
                    int rlo = row0 + m_base + mt * 16 + (lane >> 2);
                    g_cmin[(size_t)rlo * NGROUP + grp] = __float2bfloat16_rn(vlo);
                    g_cmin[(size_t)(rlo + 8) * NGROUP + grp] = __float2bfloat16_rn(vhi);
                }
            }
        }
    }
}

// ---------------------------------------------------------------------------
// 6) Sweep 2: exact fp32 rescore of candidate groups; warp per row.
// ---------------------------------------------------------------------------
__global__ void __launch_bounds__(256, 4) k_pick(const float* __restrict__ e) {
    const int tid = threadIdx.x, lane = tid & 31, wid = tid >> 5;
    const int row = blockIdx.x * 8 + wid;

    // load this row's group mins: lane owns groups [lane*32, lane*32+32)
    const uint4* cm4 = (const uint4*)(g_cmin + (size_t)row * NGROUP) + lane * 4;
    float v[32];
    float gmin = 3.402823466e38f;
#pragma unroll
    for (int j = 0; j < 4; j++) {
        uint4 q = cm4[j];
        const uint32_t w[4] = {q.x, q.y, q.z, q.w};
#pragma unroll
        for (int h = 0; h < 4; h++) {
            v[j * 8 + h * 2 + 0] = __bfloat162float(__ushort_as_bfloat16((unsigned short)(w[h] & 0xffff)));
            v[j * 8 + h * 2 + 1] = __bfloat162float(__ushort_as_bfloat16((unsigned short)(w[h] >> 16)));
        }
    }
#pragma unroll
    for (int j = 0; j < 32; j++) gmin = fminf(gmin, v[j]);
#pragma unroll
    for (int off = 16; off; off >>= 1)
        gmin = fminf(gmin, __shfl_xor_sync(0xffffffffu, gmin, off));
    const float thr = gmin + MARGIN;

    uint32_t lmask = 0;
#pragma unroll
    for (int j = 0; j < 32; j++) if (v[j] <= thr) lmask |= (1u << j);

    // x row in registers (lane covers dims lane*8..lane*8+7)
    const float4* xr = (const float4*)(g_xr + (size_t)row * DIMS) + lane * 2;
    float4 x0 = xr[0], x1 = xr[1];
    const float xx = g_xx[row];

    float minv = 3.402823466e38f;
    int mini = 0x7fffffff;

    for (int src = 0; src < 32; src++) {
        uint32_t m = __shfl_sync(0xffffffffu, lmask, src);
        while (m) {
            int bit = __ffs(m) - 1;
            m &= m - 1;
            int grp = src * 32 + bit;
#pragma unroll
            for (int cc = 0; cc < 8; cc++) {
                int code = grp * 8 + cc;
                const float4* er = (const float4*)(e + (size_t)code * DIMS) + lane * 2;
                float4 e0 = er[0], e1 = er[1];
                float t = x0.x * e0.x;
                t = fmaf(x0.y, e0.y, t); t = fmaf(x0.z, e0.z, t);
                t = fmaf(x0.w, e0.w, t); t = fmaf(x1.x, e1.x, t);
                t = fmaf(x1.y, e1.y, t); t = fmaf(x1.z, e1.z, t);
                t = fmaf(x1.w, e1.w, t);
#pragma unroll
                for (int off = 16; off; off >>= 1)
                    t += __shfl_xor_sync(0xffffffffu, t, off);
                float s = (xx + g_ce[code]) - 2.0f * t;
                if (s < minv || (s == minv && code < mini)) { minv = s; mini = code; }
            }
        }
    }
    if (lane == 0) g_idx[row] = mini;
}

// ---------------------------------------------------------------------------
// 7) gather + out + loss partials
__global__ void k_out(const float* __restrict__ x, const float* __restrict__ e,
                      float* __restrict__ dout) {
    __shared__ float t[32][33];
    __shared__ int sidx[32];
    __shared__ float red[256];
    const int b = blockIdx.z, c0 = blockIdx.y * 32, hw0 = blockIdx.x * 32;
    const int tx = threadIdx.x, ty = threadIdx.y;
    if (ty == 0) {
        int n = b * 1024 + hw0 + tx;
        int i = g_idx[n];
        sidx[tx] = i;
        if (blockIdx.y == 0) dout[IDX_OFF + n] = (float)i;
    }
    __syncthreads();
#pragma unroll
    for (int j = 0; j < 4; j++)
        t[ty + j * 8][tx] = e[(size_t)sidx[ty + j * 8] * DIMS + c0 + tx];
    __syncthreads();
    float lacc = 0.f;
#pragma unroll
    for (int j = 0; j < 4; j++) {
        int cl = ty + j * 8;
        size_t o = (size_t)b * 262144 + (size_t)(c0 + cl) * 1024 + hw0 + tx;
        float q = t[tx][cl];
        dout[o] = q;
        float d = q - x[o];
        lacc = fmaf(d, d, lacc);
    }
    int tid = ty * 32 + tx;
    red[tid] = lacc;
    __syncthreads();
    for (int s = 128; s; s >>= 1) {
        if (tid < s) red[tid] += red[tid + s];
        __syncthreads();
    }
    if (tid == 0) g_part[(blockIdx.z * 8 + blockIdx.y) * 32 + blockIdx.x] = red[0];
}

__global__ void k_loss(float* __restrict__ dout) {
    __shared__ double rd[256];
    double s = 0.0;
    for (int i = threadIdx.x; i < 4096; i += 256) s += (double)g_part[i];
    rd[threadIdx.x] = s;
    __syncthreads();
    for (int st = 128; st; st >>= 1) {
        if (threadIdx.x < st) rd[threadIdx.x] += rd[threadIdx.x + st];
        __syncthreads();
    }
    if (threadIdx.x == 0)
        dout[LOSS_OFF] = (float)(rd[0] * (1.25 / (double)OUT_ELEMS));
}

// ---------------------------------------------------------------------------
extern "C" void kernel_launch(void* const* d_in, const int* in_sizes, int n_in,
                              void* d_out, int out_size) {
    const float* x = (const float*)d_in[0];
    const float* e = (const float*)d_in[1];
    float* out = (float*)d_out;

    cudaFuncSetAttribute(k_gemm, cudaFuncAttributeMaxDynamicSharedMemorySize,
                         SMEM_SZ);

    k_trx<<<dim3(32, 8, 16), dim3(32, 8)>>>(x);
    k_xx<<<64, 256>>>(x);
    k_pe<<<1024, 256>>>(e);
    k_eb<<<2048, 256>>>(e);
    k_gemm<<<128, 256, SMEM_SZ>>>();
    k_pick<<<2048, 256>>>(e);
    k_out<<<dim3(32, 8, 16), dim3(32, 8)>>>(x, e, out);
    k_loss<<<1, 256>>>(out);
}

// round 8
// speedup vs baseline: 6.5478x; 2.1191x over previous
#include <cuda_runtime.h>
#include <cuda_bf16.h>
#include <cstdint>

#define N_ROWS   16384
#define DIMS     256
#define K_CODES  8192
#define OUT_ELEMS 4194304
#define LOSS_OFF  4194304
#define IDX_OFF   4194305
#define NGROUP   512           // 8192 codes / 16 per lane-local group
#define MARGIN   0.125f

// device scratch (allocation-free rule)
__device__ float g_xr[N_ROWS * DIMS];            // transposed x fp32
__device__ __nv_bfloat16 g_xb[N_ROWS * DIMS];    // transposed x bf16
__device__ __nv_bfloat16 g_ebh[K_CODES * DIMS];  // E bf16
__device__ float g_xx[N_ROWS];
__device__ float g_ce[K_CODES];
__device__ __nv_bfloat16 g_cmin[N_ROWS * NGROUP]; // approx lane-group mins
__device__ int   g_idx[N_ROWS];
__device__ float g_part[4096];

// ---------------- PTX helpers ----------------
static __device__ __forceinline__ uint32_t smem_u32(const void* p) {
    uint32_t a;
    asm("{ .reg .u64 t; cvta.to.shared.u64 t, %1; cvt.u32.u64 %0, t; }"
        : "=r"(a) : "l"(p));
    return a;
}
#define CP16(dst, src) asm volatile("cp.async.cg.shared.global [%0], [%1], 16;" :: "r"(dst), "l"(src))
#define CP_COMMIT()    asm volatile("cp.async.commit_group;" ::: "memory")
#define CP_WAIT0()     asm volatile("cp.async.wait_group 0;" ::: "memory")

#define LDSM_X4(r0, r1, r2, r3, a) \
    asm volatile("ldmatrix.sync.aligned.m8n8.x4.shared.b16 {%0,%1,%2,%3}, [%4];" \
        : "=r"(r0), "=r"(r1), "=r"(r2), "=r"(r3) : "r"(a))
#define MMA16816(d, a, b) \
    asm volatile("mma.sync.aligned.m16n8k16.row.col.f32.bf16.bf16.f32 " \
        "{%0,%1,%2,%3}, {%4,%5,%6,%7}, {%8,%9}, {%0,%1,%2,%3};" \
        : "+f"((d)[0]), "+f"((d)[1]), "+f"((d)[2]), "+f"((d)[3]) \
        : "r"((a)[0]), "r"((a)[1]), "r"((a)[2]), "r"((a)[3]), "r"((b)[0]), "r"((b)[1]))

// swizzled 16B-unit offset within a [128 rows x 512B] tile
static __device__ __forceinline__ uint32_t sw_off(int r, int u) {
    return ((uint32_t)r << 9) + (uint32_t)(((u ^ (r & 7)) & 31) << 4);
}

// SMEM map for k_gemm (bytes)
#define SM_X   0
#define SM_E0  65536
#define SM_E1  131072
#define SM_CE  196608
#define SMEM_SZ 229376

// ---------------------------------------------------------------------------
// 1) transpose: x [b,c,h,w] -> g_xr fp32 and g_xb bf16, [n][c]
__global__ void k_trx(const float* __restrict__ x) {
    __shared__ float t[32][33];
    const int b = blockIdx.z, c0 = blockIdx.y * 32, hw0 = blockIdx.x * 32;
    const int tx = threadIdx.x, ty = threadIdx.y;
#pragma unroll
    for (int j = 0; j < 4; j++)
        t[ty + j * 8][tx] = x[(size_t)b * 262144 + (size_t)(c0 + ty + j * 8) * 1024 + hw0 + tx];
    __syncthreads();
#pragma unroll
    for (int j = 0; j < 4; j++) {
        int n = b * 1024 + hw0 + ty + j * 8;
        float v = t[tx][ty + j * 8];
        g_xr[(size_t)n * DIMS + c0 + tx] = v;
        g_xb[(size_t)n * DIMS + c0 + tx] = __float2bfloat16_rn(v);
    }
}

// 2) ||x||^2
__global__ void k_xx(const float* __restrict__ x) {
    int n = blockIdx.x * 256 + threadIdx.x;
    int b = n >> 10, hw = n & 1023;
    const float* p = x + (size_t)b * 262144 + hw;
    float s0 = 0.f, s1 = 0.f, s2 = 0.f, s3 = 0.f;
#pragma unroll 8
    for (int c = 0; c < 256; c += 4) {
        float v0 = p[(size_t)(c + 0) * 1024], v1 = p[(size_t)(c + 1) * 1024];
        float v2 = p[(size_t)(c + 2) * 1024], v3 = p[(size_t)(c + 3) * 1024];
        s0 = fmaf(v0, v0, s0); s1 = fmaf(v1, v1, s1);
        s2 = fmaf(v2, v2, s2); s3 = fmaf(v3, v3, s3);
    }
    g_xx[n] = (s0 + s1) + (s2 + s3);
}

// 3) E prep: ||e||^2 + bf16 convert (one warp per code row)
__global__ void k_prep_e(const float* __restrict__ e) {
    int w = threadIdx.x >> 5, lane = threadIdx.x & 31;
    int row = blockIdx.x * 8 + w;
    const float4* p = (const float4*)(e + (size_t)row * DIMS);
    float4 v0 = p[lane], v1 = p[lane + 32];
    float s = v0.x * v0.x + v0.y * v0.y + v0.z * v0.z + v0.w * v0.w +
              v1.x * v1.x + v1.y * v1.y + v1.z * v1.z + v1.w * v1.w;
    uint2* q = (uint2*)(g_ebh + (size_t)row * DIMS);
    uint32_t a0 = ((uint32_t)__bfloat16_as_ushort(__float2bfloat16_rn(v0.y)) << 16) |
                  (uint32_t)__bfloat16_as_ushort(__float2bfloat16_rn(v0.x));
    uint32_t a1 = ((uint32_t)__bfloat16_as_ushort(__float2bfloat16_rn(v0.w)) << 16) |
                  (uint32_t)__bfloat16_as_ushort(__float2bfloat16_rn(v0.z));
    uint32_t b0 = ((uint32_t)__bfloat16_as_ushort(__float2bfloat16_rn(v1.y)) << 16) |
                  (uint32_t)__bfloat16_as_ushort(__float2bfloat16_rn(v1.x));
    uint32_t b1 = ((uint32_t)__bfloat16_as_ushort(__float2bfloat16_rn(v1.w)) << 16) |
                  (uint32_t)__bfloat16_as_ushort(__float2bfloat16_rn(v1.z));
    q[lane] = make_uint2(a0, a1);
    q[lane + 32] = make_uint2(b0, b1);
#pragma unroll
    for (int off = 16; off; off >>= 1) s += __shfl_xor_sync(0xffffffffu, s, off);
    if (lane == 0) g_ce[row] = s;
}

// ---------------------------------------------------------------------------
// 4) Sweep 1: bf16 mma.sync GEMM, approx s = ce - 2*dot, lane-local group mins
//    (group = 16 codes one lane owns: 2 cols x 8 n-tiles at fixed quad q).
//    grid 128, block 256 = 8 warps (4 m x 2 n), warp tile 32 rows x 64 codes.
// ---------------------------------------------------------------------------
__global__ void __launch_bounds__(256, 1) k_gemm() {
    extern __shared__ char smem[];
    const uint32_t sb = smem_u32(smem);
    const int tid = threadIdx.x, lane = tid & 31, wid = tid >> 5;
    const int warp_m = wid & 3, warp_n = wid >> 2;
    const int m_base = warp_m * 32, n_base = warp_n * 64;
    const int row0 = blockIdx.x * 128;
    const int q = lane & 3;

    // prologue: X tile (swizzled), ce table, E chunk0 via cp.async
#pragma unroll
    for (int j = 0; j < 16; j++) {
        int idx = tid + j * 256;
        int r = idx >> 5, u = idx & 31;
        CP16(sb + SM_X + sw_off(r, u), g_xb + (size_t)(row0 + r) * DIMS + u * 8);
    }
#pragma unroll
    for (int j = 0; j < 8; j++) {
        int idx = tid + j * 256;
        CP16(sb + SM_CE + idx * 16, g_ce + idx * 4);
    }
#pragma unroll
    for (int j = 0; j < 16; j++) {
        int idx = tid + j * 256;
        int r = idx >> 5, u = idx & 31;
        CP16(sb + SM_E0 + sw_off(r, u), g_ebh + (size_t)r * DIMS + u * 8);
    }
    CP_COMMIT();

    // ldmatrix lane address components
    const int a_r = (lane & 15), a_u = (lane >> 4);
    const int b_g = lane >> 3;                  // 0..3: (ntoff, khalf)
    const int b_nt = b_g >> 1, b_kh = b_g & 1;
    const int b_r = lane & 7;

    for (int c = 0; c < 64; c++) {
        CP_WAIT0();
        __syncthreads();
        const uint32_t eb = sb + ((c & 1) ? SM_E1 : SM_E0);
        if (c < 63) {
            const uint32_t nb = sb + ((c & 1) ? SM_E0 : SM_E1);
            const __nv_bfloat16* src = g_ebh + (size_t)(c + 1) * 128 * DIMS;
#pragma unroll
            for (int j = 0; j < 16; j++) {
                int idx = tid + j * 256;
                int r = idx >> 5, u = idx & 31;
                CP16(nb + sw_off(r, u), src + (size_t)r * DIMS + u * 8);
            }
            CP_COMMIT();
        }

        float acc[2][8][4];
#pragma unroll
        for (int mt = 0; mt < 2; mt++)
#pragma unroll
            for (int nt = 0; nt < 8; nt++)
#pragma unroll
                for (int z = 0; z < 4; z++) acc[mt][nt][z] = 0.f;

#pragma unroll
        for (int kt = 0; kt < 16; kt++) {
            uint32_t a[2][4], b[8][2];
#pragma unroll
            for (int mt = 0; mt < 2; mt++) {
                uint32_t addr = sb + SM_X +
                    sw_off(m_base + mt * 16 + a_r, kt * 2 + a_u);
                LDSM_X4(a[mt][0], a[mt][1], a[mt][2], a[mt][3], addr);
            }
#pragma unroll
            for (int np = 0; np < 4; np++) {   // pairs of n-tiles
                uint32_t addr = eb +
                    sw_off(n_base + (np * 2 + b_nt) * 8 + b_r, kt * 2 + b_kh);
                LDSM_X4(b[np * 2][0], b[np * 2][1],
                        b[np * 2 + 1][0], b[np * 2 + 1][1], addr);
            }
#pragma unroll
            for (int mt = 0; mt < 2; mt++)
#pragma unroll
                for (int nt = 0; nt < 8; nt++)
                    MMA16816(acc[mt][nt], a[mt], b[nt]);
        }

        // epilogue: lane-local min over 8 n-tiles (no shuffles)
        float mn[2][2] = {{3.4e38f, 3.4e38f}, {3.4e38f, 3.4e38f}};
#pragma unroll
        for (int nt = 0; nt < 8; nt++) {
            int col = c * 128 + n_base + nt * 8 + q * 2;
            float2 ce2;
            asm volatile("ld.shared.v2.f32 {%0,%1}, [%2];"
                         : "=f"(ce2.x), "=f"(ce2.y)
                         : "r"(sb + SM_CE + (uint32_t)col * 4));
#pragma unroll
            for (int mt = 0; mt < 2; mt++) {
                float vlo = fminf(fmaf(-2.f, acc[mt][nt][0], ce2.x),
                                  fmaf(-2.f, acc[mt][nt][1], ce2.y));
                float vhi = fminf(fmaf(-2.f, acc[mt][nt][2], ce2.x),
                                  fmaf(-2.f, acc[mt][nt][3], ce2.y));
                mn[mt][0] = fminf(mn[mt][0], vlo);
                mn[mt][1] = fminf(mn[mt][1], vhi);
            }
        }
        const int grp = c * 8 + warp_n * 4 + q;
#pragma unroll
        for (int mt = 0; mt < 2; mt++) {
            int rlo = row0 + m_base + mt * 16 + (lane >> 2);
            g_cmin[(size_t)rlo * NGROUP + grp] = __float2bfloat16_rn(mn[mt][0]);
            g_cmin[(size_t)(rlo + 8) * NGROUP + grp] = __float2bfloat16_rn(mn[mt][1]);
        }
    }
}

// ---------------------------------------------------------------------------
// 5) Sweep 2: exact fp32 rescore of candidate groups; warp per row.
//    group grp -> codes {(grp>>3)*128 + ((grp>>2)&1)*64 + (grp&3)*2 + nt*8 + {0,1}}
// ---------------------------------------------------------------------------
__global__ void __launch_bounds__(256, 4) k_pick(const float* __restrict__ e) {
    const int tid = threadIdx.x, lane = tid & 31, wid = tid >> 5;
    const int row = blockIdx.x * 8 + wid;

    // lane owns 16 groups: grp = lane*16 + j
    const uint4* cm4 = (const uint4*)(g_cmin + (size_t)row * NGROUP) + lane * 2;
    float v[16];
    float gmin = 3.402823466e38f;
#pragma unroll
    for (int j = 0; j < 2; j++) {
        uint4 qq = cm4[j];
        const uint32_t w[4] = {qq.x, qq.y, qq.z, qq.w};
#pragma unroll
        for (int h = 0; h < 4; h++) {
            v[j * 8 + h * 2 + 0] = __bfloat162float(__ushort_as_bfloat16((unsigned short)(w[h] & 0xffff)));
            v[j * 8 + h * 2 + 1] = __bfloat162float(__ushort_as_bfloat16((unsigned short)(w[h] >> 16)));
        }
    }
#pragma unroll
    for (int j = 0; j < 16; j++) gmin = fminf(gmin, v[j]);
#pragma unroll
    for (int off = 16; off; off >>= 1)
        gmin = fminf(gmin, __shfl_xor_sync(0xffffffffu, gmin, off));
    const float thr = gmin + MARGIN;

    uint32_t lmask = 0;
#pragma unroll
    for (int j = 0; j < 16; j++) if (v[j] <= thr) lmask |= (1u << j);

    const float4* xr = (const float4*)(g_xr + (size_t)row * DIMS) + lane * 2;
    float4 x0 = xr[0], x1 = xr[1];
    const float xx = g_xx[row];

    float minv = 3.402823466e38f;
    int mini = 0x7fffffff;

    for (int src = 0; src < 32; src++) {
        uint32_t m = __shfl_sync(0xffffffffu, lmask, src);
        while (m) {
            int bit = __ffs(m) - 1;
            m &= m - 1;
            int grp = src * 16 + bit;
            int base = (grp >> 3) * 128 + ((grp >> 2) & 1) * 64 + (grp & 3) * 2;
#pragma unroll
            for (int nt = 0; nt < 8; nt++) {
#pragma unroll
                for (int cc = 0; cc < 2; cc++) {
                    int code = base + nt * 8 + cc;
                    const float4* er = (const float4*)(e + (size_t)code * DIMS) + lane * 2;
                    float4 e0 = er[0], e1 = er[1];
                    float t = x0.x * e0.x;
                    t = fmaf(x0.y, e0.y, t); t = fmaf(x0.z, e0.z, t);
                    t = fmaf(x0.w, e0.w, t); t = fmaf(x1.x, e1.x, t);
                    t = fmaf(x1.y, e1.y, t); t = fmaf(x1.z, e1.z, t);
                    t = fmaf(x1.w, e1.w, t);
#pragma unroll
                    for (int off = 16; off; off >>= 1)
                        t += __shfl_xor_sync(0xffffffffu, t, off);
                    float s = (xx + g_ce[code]) - 2.0f * t;
                    if (s < minv || (s == minv && code < mini)) { minv = s; mini = code; }
                }
            }
        }
    }
    if (lane == 0) g_idx[row] = mini;
}

// ---------------------------------------------------------------------------
// 6) gather + out + loss partials
__global__ void k_out(const float* __restrict__ x, const float* __restrict__ e,
                      float* __restrict__ dout) {
    __shared__ float t[32][33];
    __shared__ int sidx[32];
    __shared__ float red[256];
    const int b = blockIdx.z, c0 = blockIdx.y * 32, hw0 = blockIdx.x * 32;
    const int tx = threadIdx.x, ty = threadIdx.y;
    if (ty == 0) {
        int n = b * 1024 + hw0 + tx;
        int i = g_idx[n];
        sidx[tx] = i;
        if (blockIdx.y == 0) dout[IDX_OFF + n] = (float)i;
    }
    __syncthreads();
#pragma unroll
    for (int j = 0; j < 4; j++)
        t[ty + j * 8][tx] = e[(size_t)sidx[ty + j * 8] * DIMS + c0 + tx];
    __syncthreads();
    float lacc = 0.f;
#pragma unroll
    for (int j = 0; j < 4; j++) {
        int cl = ty + j * 8;
        size_t o = (size_t)b * 262144 + (size_t)(c0 + cl) * 1024 + hw0 + tx;
        float qv = t[tx][cl];
        dout[o] = qv;
        float d = qv - x[o];
        lacc = fmaf(d, d, lacc);
    }
    int tid = ty * 32 + tx;
    red[tid] = lacc;
    __syncthreads();
    for (int s = 128; s; s >>= 1) {
        if (tid < s) red[tid] += red[tid + s];
        __syncthreads();
    }
    if (tid == 0) g_part[(blockIdx.z * 8 + blockIdx.y) * 32 + blockIdx.x] = red[0];
}

__global__ void k_loss(float* __restrict__ dout) {
    __shared__ double rd[256];
    double s = 0.0;
    for (int i = threadIdx.x; i < 4096; i += 256) s += (double)g_part[i];
    rd[threadIdx.x] = s;
    __syncthreads();
    for (int st = 128; st; st >>= 1) {
        if (threadIdx.x < st) rd[threadIdx.x] += rd[threadIdx.x + st];
        __syncthreads();
    }
    if (threadIdx.x == 0)
        dout[LOSS_OFF] = (float)(rd[0] * (1.25 / (double)OUT_ELEMS));
}

// ---------------------------------------------------------------------------
extern "C" void kernel_launch(void* const* d_in, const int* in_sizes, int n_in,
                              void* d_out, int out_size) {
    const float* x = (const float*)d_in[0];
    const float* e = (const float*)d_in[1];
    float* out = (float*)d_out;

    cudaFuncSetAttribute(k_gemm, cudaFuncAttributeMaxDynamicSharedMemorySize,
                         SMEM_SZ);

    k_trx<<<dim3(32, 8, 16), dim3(32, 8)>>>(x);
    k_xx<<<64, 256>>>(x);
    k_prep_e<<<1024, 256>>>(e);
    k_gemm<<<128, 256, SMEM_SZ>>>();
    k_pick<<<2048, 256>>>(e);
    k_out<<<dim3(32, 8, 16), dim3(32, 8)>>>(x, e, out);
    k_loss<<<1, 256>>>(out);
}

// round 11
// speedup vs baseline: 6.5581x; 1.0016x over previous
#include <cuda_runtime.h>
#include <cuda_bf16.h>
#include <cstdint>

#define N_ROWS   16384
#define DIMS     256
#define K_CODES  8192
#define OUT_ELEMS 4194304
#define LOSS_OFF  4194304
#define IDX_OFF   4194305
#define NGROUP   512           // 8192 codes / 16 per lane-local group
#define MARGIN   0.125f

// device scratch (allocation-free rule)
__device__ float g_xr[N_ROWS * DIMS];            // transposed x fp32
__device__ __nv_bfloat16 g_xb[N_ROWS * DIMS];    // transposed x bf16
__device__ __nv_bfloat16 g_ebh[K_CODES * DIMS];  // E bf16
__device__ float g_xx[N_ROWS];
__device__ float g_ce[K_CODES];
__device__ __nv_bfloat16 g_cmin[N_ROWS * NGROUP]; // approx lane-group mins
__device__ int   g_idx[N_ROWS];
__device__ float g_minv[N_ROWS];                  // winning distance per row

// ---------------- PTX helpers ----------------
static __device__ __forceinline__ uint32_t smem_u32(const void* p) {
    uint32_t a;
    asm("{ .reg .u64 t; cvta.to.shared.u64 t, %1; cvt.u32.u64 %0, t; }"
        : "=r"(a) : "l"(p));
    return a;
}
#define CP16(dst, src) asm volatile("cp.async.cg.shared.global [%0], [%1], 16;" :: "r"(dst), "l"(src))
#define CP_COMMIT()    asm volatile("cp.async.commit_group;" ::: "memory")
#define CP_WAIT0()     asm volatile("cp.async.wait_group 0;" ::: "memory")

#define LDSM_X4(r0, r1, r2, r3, a) \
    asm volatile("ldmatrix.sync.aligned.m8n8.x4.shared.b16 {%0,%1,%2,%3}, [%4];" \
        : "=r"(r0), "=r"(r1), "=r"(r2), "=r"(r3) : "r"(a))
#define MMA16816(d, a, b) \
    asm volatile("mma.sync.aligned.m16n8k16.row.col.f32.bf16.bf16.f32 " \
        "{%0,%1,%2,%3}, {%4,%5,%6,%7}, {%8,%9}, {%0,%1,%2,%3};" \
        : "+f"((d)[0]), "+f"((d)[1]), "+f"((d)[2]), "+f"((d)[3]) \
        : "r"((a)[0]), "r"((a)[1]), "r"((a)[2]), "r"((a)[3]), "r"((b)[0]), "r"((b)[1]))

// swizzled 16B-unit offset within a [128 rows x 512B] tile
static __device__ __forceinline__ uint32_t sw_off(int r, int u) {
    return ((uint32_t)r << 9) + (uint32_t)(((u ^ (r & 7)) & 31) << 4);
}

// SMEM map for k_gemm (bytes)
#define SM_X   0
#define SM_E0  65536
#define SM_E1  131072
#define SM_CE  196608
#define SMEM_SZ 229376

// ---------------------------------------------------------------------------
// 1) fused transpose + xx + bf16: x [b,c,h,w] -> g_xr, g_xb, g_xx
//    grid (32 hw-blocks, 16 b), block (32, 8)
__global__ void k_trx(const float* __restrict__ x) {
    __shared__ float t[256][33];
    __shared__ float sxx[8][33];
    const int b = blockIdx.y, hw0 = blockIdx.x * 32;
    const int tx = threadIdx.x, ty = threadIdx.y;
    const int tid = ty * 32 + tx;
    const int n0 = b * 1024 + hw0;

    float px = 0.f;
#pragma unroll
    for (int j = 0; j < 32; j++) {
        int c = ty + j * 8;
        float v = x[(size_t)b * 262144 + (size_t)c * 1024 + hw0 + tx];
        t[c][tx] = v;
        px = fmaf(v, v, px);
    }
    sxx[ty][tx] = px;
    __syncthreads();

#pragma unroll
    for (int r = 0; r < 32; r++) {
        float v = t[tid][r];
        g_xr[(size_t)(n0 + r) * DIMS + tid] = v;
        g_xb[(size_t)(n0 + r) * DIMS + tid] = __float2bfloat16_rn(v);
    }
    if (tid < 32) {
        float s = 0.f;
#pragma unroll
        for (int j = 0; j < 8; j++) s += sxx[j][tid];
        g_xx[n0 + tid] = s;
    }
}

// 2) E prep: ||e||^2 + bf16 convert (one warp per code row)
__global__ void k_prep_e(const float* __restrict__ e) {
    int w = threadIdx.x >> 5, lane = threadIdx.x & 31;
    int row = blockIdx.x * 8 + w;
    const float4* p = (const float4*)(e + (size_t)row * DIMS);
    float4 v0 = p[lane], v1 = p[lane + 32];
    float s = v0.x * v0.x + v0.y * v0.y + v0.z * v0.z + v0.w * v0.w +
              v1.x * v1.x + v1.y * v1.y + v1.z * v1.z + v1.w * v1.w;
    uint2* q = (uint2*)(g_ebh + (size_t)row * DIMS);
    uint32_t a0 = ((uint32_t)__bfloat16_as_ushort(__float2bfloat16_rn(v0.y)) << 16) |
                  (uint32_t)__bfloat16_as_ushort(__float2bfloat16_rn(v0.x));
    uint32_t a1 = ((uint32_t)__bfloat16_as_ushort(__float2bfloat16_rn(v0.w)) << 16) |
                  (uint32_t)__bfloat16_as_ushort(__float2bfloat16_rn(v0.z));
    uint32_t b0 = ((uint32_t)__bfloat16_as_ushort(__float2bfloat16_rn(v1.y)) << 16) |
                  (uint32_t)__bfloat16_as_ushort(__float2bfloat16_rn(v1.x));
    uint32_t b1 = ((uint32_t)__bfloat16_as_ushort(__float2bfloat16_rn(v1.w)) << 16) |
                  (uint32_t)__bfloat16_as_ushort(__float2bfloat16_rn(v1.z));
    q[lane] = make_uint2(a0, a1);
    q[lane + 32] = make_uint2(b0, b1);
#pragma unroll
    for (int off = 16; off; off >>= 1) s += __shfl_xor_sync(0xffffffffu, s, off);
    if (lane == 0) g_ce[row] = s;
}

// ---------------------------------------------------------------------------
// 3) Sweep 1: bf16 mma.sync GEMM; A fragments REGISTER-RESIDENT across all
//    64 chunks (X is loop-invariant). Per kt only 4 B-LDSM_X4 remain.
//    grid 128, block 256 = 8 warps (4 m x 2 n), warp tile 32 rows x 64 codes.
// ---------------------------------------------------------------------------
__global__ void __launch_bounds__(256, 1) k_gemm() {
    extern __shared__ char smem[];
    const uint32_t sb = smem_u32(smem);
    const int tid = threadIdx.x, lane = tid & 31, wid = tid >> 5;
    const int warp_m = wid & 3, warp_n = wid >> 2;
    const int m_base = warp_m * 32, n_base = warp_n * 64;
    const int row0 = blockIdx.x * 128;
    const int q = lane & 3;

    // prologue: X tile (swizzled), ce table, E chunk0 via cp.async
#pragma unroll
    for (int j = 0; j < 16; j++) {
        int idx = tid + j * 256;
        int r = idx >> 5, u = idx & 31;
        CP16(sb + SM_X + sw_off(r, u), g_xb + (size_t)(row0 + r) * DIMS + u * 8);
    }
#pragma unroll
    for (int j = 0; j < 8; j++) {
        int idx = tid + j * 256;
        CP16(sb + SM_CE + idx * 16, g_ce + idx * 4);
    }
#pragma unroll
    for (int j = 0; j < 16; j++) {
        int idx = tid + j * 256;
        int r = idx >> 5, u = idx & 31;
        CP16(sb + SM_E0 + sw_off(r, u), g_ebh + (size_t)r * DIMS + u * 8);
    }
    CP_COMMIT();
    CP_WAIT0();
    __syncthreads();

    // A fragments for the whole k-range, resident in registers
    const int a_r = (lane & 15), a_u = (lane >> 4);
    uint32_t a[2][16][4];
#pragma unroll
    for (int kt = 0; kt < 16; kt++)
#pragma unroll
        for (int mt = 0; mt < 2; mt++) {
            uint32_t addr = sb + SM_X +
                sw_off(m_base + mt * 16 + a_r, kt * 2 + a_u);
            LDSM_X4(a[mt][kt][0], a[mt][kt][1], a[mt][kt][2], a[mt][kt][3], addr);
        }

    const int b_g = lane >> 3;
    const int b_nt = b_g >> 1, b_kh = b_g & 1;
    const int b_r = lane & 7;

    for (int c = 0; c < 64; c++) {
        if (c > 0) {
            CP_WAIT0();
            __syncthreads();
        }
        const uint32_t eb = sb + ((c & 1) ? SM_E1 : SM_E0);
        if (c < 63) {
            const uint32_t nb = sb + ((c & 1) ? SM_E0 : SM_E1);
            const __nv_bfloat16* src = g_ebh + (size_t)(c + 1) * 128 * DIMS;
#pragma unroll
            for (int j = 0; j < 16; j++) {
                int idx = tid + j * 256;
                int r = idx >> 5, u = idx & 31;
                CP16(nb + sw_off(r, u), src + (size_t)r * DIMS + u * 8);
            }
            CP_COMMIT();
        }

        float acc[2][8][4];
#pragma unroll
        for (int mt = 0; mt < 2; mt++)
#pragma unroll
            for (int nt = 0; nt < 8; nt++)
#pragma unroll
                for (int z = 0; z < 4; z++) acc[mt][nt][z] = 0.f;

#pragma unroll
        for (int kt = 0; kt < 16; kt++) {
            uint32_t b[8][2];
#pragma unroll
            for (int np = 0; np < 4; np++) {
                uint32_t addr = eb +
                    sw_off(n_base + (np * 2 + b_nt) * 8 + b_r, kt * 2 + b_kh);
                LDSM_X4(b[np * 2][0], b[np * 2][1],
                        b[np * 2 + 1][0], b[np * 2 + 1][1], addr);
            }
#pragma unroll
            for (int mt = 0; mt < 2; mt++)
#pragma unroll
                for (int nt = 0; nt < 8; nt++)
                    MMA16816(acc[mt][nt], a[mt][kt], b[nt]);
        }

        // epilogue: lane-local min over 8 n-tiles (no shuffles)
        float mn[2][2] = {{3.4e38f, 3.4e38f}, {3.4e38f, 3.4e38f}};
#pragma unroll
        for (int nt = 0; nt < 8; nt++) {
            int col = c * 128 + n_base + nt * 8 + q * 2;
            float2 ce2;
            asm volatile("ld.shared.v2.f32 {%0,%1}, [%2];"
                         : "=f"(ce2.x), "=f"(ce2.y)
                         : "r"(sb + SM_CE + (uint32_t)col * 4));
#pragma unroll
            for (int mt = 0; mt < 2; mt++) {
                float vlo = fminf(fmaf(-2.f, acc[mt][nt][0], ce2.x),
                                  fmaf(-2.f, acc[mt][nt][1], ce2.y));
                float vhi = fminf(fmaf(-2.f, acc[mt][nt][2], ce2.x),
                                  fmaf(-2.f, acc[mt][nt][3], ce2.y));
                mn[mt][0] = fminf(mn[mt][0], vlo);
                mn[mt][1] = fminf(mn[mt][1], vhi);
            }
        }
        const int grp = c * 8 + warp_n * 4 + q;
#pragma unroll
        for (int mt = 0; mt < 2; mt++) {
            int rlo = row0 + m_base + mt * 16 + (lane >> 2);
            g_cmin[(size_t)rlo * NGROUP + grp] = __float2bfloat16_rn(mn[mt][0]);
            g_cmin[(size_t)(rlo + 8) * NGROUP + grp] = __float2bfloat16_rn(mn[mt][1]);
        }
    }
}

// ---------------------------------------------------------------------------
// 4) Sweep 2: exact fp32 rescore of candidate groups; warp per row.
//    group grp -> codes {(grp>>3)*128 + ((grp>>2)&1)*64 + (grp&3)*2 + nt*8 + {0,1}}
// ---------------------------------------------------------------------------
__global__ void __launch_bounds__(256, 4) k_pick(const float* __restrict__ e) {
    const int tid = threadIdx.x, lane = tid & 31, wid = tid >> 5;
    const int row = blockIdx.x * 8 + wid;

    const uint4* cm4 = (const uint4*)(g_cmin + (size_t)row * NGROUP) + lane * 2;
    float v[16];
    float gmin = 3.402823466e38f;
#pragma unroll
    for (int j = 0; j < 2; j++) {
        uint4 qq = cm4[j];
        const uint32_t w[4] = {qq.x, qq.y, qq.z, qq.w};
#pragma unroll
        for (int h = 0; h < 4; h++) {
            v[j * 8 + h * 2 + 0] = __bfloat162float(__ushort_as_bfloat16((unsigned short)(w[h] & 0xffff)));
            v[j * 8 + h * 2 + 1] = __bfloat162float(__ushort_as_bfloat16((unsigned short)(w[h] >> 16)));
        }
    }
#pragma unroll
    for (int j = 0; j < 16; j++) gmin = fminf(gmin, v[j]);
#pragma unroll
    for (int off = 16; off; off >>= 1)
        gmin = fminf(gmin, __shfl_xor_sync(0xffffffffu, gmin, off));
    const float thr = gmin + MARGIN;

    uint32_t lmask = 0;
#pragma unroll
    for (int j = 0; j < 16; j++) if (v[j] <= thr) lmask |= (1u << j);

    const float4* xr = (const float4*)(g_xr + (size_t)row * DIMS) + lane * 2;
    float4 x0 = xr[0], x1 = xr[1];
    const float xx = g_xx[row];

    float minv = 3.402823466e38f;
    int mini = 0x7fffffff;

    for (int src = 0; src < 32; src++) {
        uint32_t m = __shfl_sync(0xffffffffu, lmask, src);
        while (m) {
            int bit = __ffs(m) - 1;
            m &= m - 1;
            int grp = src * 16 + bit;
            int base = (grp >> 3) * 128 + ((grp >> 2) & 1) * 64 + (grp & 3) * 2;
#pragma unroll
            for (int nt = 0; nt < 8; nt++) {
#pragma unroll
                for (int cc = 0; cc < 2; cc++) {
                    int code = base + nt * 8 + cc;
                    const float4* er = (const float4*)(e + (size_t)code * DIMS) + lane * 2;
                    float4 e0 = er[0], e1 = er[1];
                    float t = x0.x * e0.x;
                    t = fmaf(x0.y, e0.y, t); t = fmaf(x0.z, e0.z, t);
                    t = fmaf(x0.w, e0.w, t); t = fmaf(x1.x, e1.x, t);
                    t = fmaf(x1.y, e1.y, t); t = fmaf(x1.z, e1.z, t);
                    t = fmaf(x1.w, e1.w, t);
#pragma unroll
                    for (int off = 16; off; off >>= 1)
                        t += __shfl_xor_sync(0xffffffffu, t, off);
                    float s = (xx + g_ce[code]) - 2.0f * t;
                    if (s < minv || (s == minv && code < mini)) { minv = s; mini = code; }
                }
            }
        }
    }
    if (lane == 0) {
        g_idx[row] = mini;
        g_minv[row] = minv;
    }
}

// ---------------------------------------------------------------------------
// 5) gather codebook rows -> out (b,c,h,w) + indices (no x re-read)
__global__ void k_out(const float* __restrict__ e, float* __restrict__ dout) {
    __shared__ float t[32][33];
    __shared__ int sidx[32];
    const int b = blockIdx.z, c0 = blockIdx.y * 32, hw0 = blockIdx.x * 32;
    const int tx = threadIdx.x, ty = threadIdx.y;
    if (ty == 0) {
        int n = b * 1024 + hw0 + tx;
        int i = g_idx[n];
        sidx[tx] = i;
        if (blockIdx.y == 0) dout[IDX_OFF + n] = (float)i;
    }
    __syncthreads();
#pragma unroll
    for (int j = 0; j < 4; j++)
        t[ty + j * 8][tx] = e[(size_t)sidx[ty + j * 8] * DIMS + c0 + tx];
    __syncthreads();
#pragma unroll
    for (int j = 0; j < 4; j++) {
        int cl = ty + j * 8;
        size_t o = (size_t)b * 262144 + (size_t)(c0 + cl) * 1024 + hw0 + tx;
        dout[o] = t[tx][cl];
    }
}

// 6) loss from per-row winning distances: loss = 1.25 * sum(minv) / OUT_ELEMS
__global__ void k_loss(float* __restrict__ dout) {
    __shared__ double rd[256];
    double s = 0.0;
    for (int i = threadIdx.x; i < N_ROWS; i += 256) s += (double)g_minv[i];
    rd[threadIdx.x] = s;
    __syncthreads();
    for (int st = 128; st; st >>= 1) {
        if (threadIdx.x < st) rd[threadIdx.x] += rd[threadIdx.x + st];
        __syncthreads();
    }
    if (threadIdx.x == 0)
        dout[LOSS_OFF] = (float)(rd[0] * (1.25 / (double)OUT_ELEMS));
}

// ---------------------------------------------------------------------------
extern "C" void kernel_launch(void* const* d_in, const int* in_sizes, int n_in,
                              void* d_out, int out_size) {
    const float* x = (const float*)d_in[0];
    const float* e = (const float*)d_in[1];
    float* out = (float*)d_out;

    cudaFuncSetAttribute(k_gemm, cudaFuncAttributeMaxDynamicSharedMemorySize,
                         SMEM_SZ);

    k_trx<<<dim3(32, 16), dim3(32, 8)>>>(x);
    k_prep_e<<<1024, 256>>>(e);
    k_gemm<<<128, 256, SMEM_SZ>>>();
    k_pick<<<2048, 256>>>(e);
    k_out<<<dim3(32, 8, 16), dim3(32, 8)>>>(e, out);
    k_loss<<<1, 256>>>(out);
}